// round 2
// baseline (speedup 1.0000x reference)
#include <cuda_runtime.h>
#include <math_constants.h>

#define NS 50000
#define NT 50000
#define NN 100000
#define DD 128

// ---------------- scratch (device globals: no runtime allocation) ----------------
static __device__ float g_x [NN * DD];
static __device__ float g_h1[NN * DD];
static __device__ float g_h2[NN * DD];
static __device__ float g_as1[NN], g_ad1[NN], g_as2[NN], g_ad2[NN];
static __device__ float g_emax1[NT], g_den1[NT];
static __device__ float g_emax2[NS], g_den2[NS];
static __device__ float g_wv[4 * DD];

// ---------------- GEMM: C[M,128] = A[M,128] @ W[128,128]^T (+ bias) --------------
// BM=64 rows/block, 256 threads, whole K=128 resident in smem.
__global__ __launch_bounds__(256, 2)
void gemm_xWt(const float* __restrict__ A, const float* __restrict__ W,
              const float* __restrict__ bias, float* __restrict__ C, int M)
{
    extern __shared__ float sm[];
    float* sA = sm;              // 64 * 132
    float* sW = sm + 64 * 132;   // 128 * 132, sW[k][j] = W[j][k]
    const int tid  = threadIdx.x;
    const int row0 = blockIdx.x * 64;

    for (int i = tid; i < 4096; i += 256) {
        int j  = i & 127;
        int k4 = (i >> 7) << 2;
        float4 w = *(const float4*)(W + j * 128 + k4);
        sW[(k4 + 0) * 132 + j] = w.x;
        sW[(k4 + 1) * 132 + j] = w.y;
        sW[(k4 + 2) * 132 + j] = w.z;
        sW[(k4 + 3) * 132 + j] = w.w;
    }
    for (int i = tid; i < 64 * 32; i += 256) {
        int r  = i >> 5;
        int k4 = (i & 31) << 2;
        int gr = row0 + r;
        float4 v = (gr < M) ? *(const float4*)(A + (size_t)gr * 128 + k4)
                            : make_float4(0.f, 0.f, 0.f, 0.f);
        *(float4*)(sA + r * 132 + k4) = v;
    }
    __syncthreads();

    const int rg = tid >> 5;
    const int cg = tid & 31;
    float acc[8][4] = {};

#pragma unroll 4
    for (int k = 0; k < 128; k += 4) {
        float w[4][4];
#pragma unroll
        for (int kk = 0; kk < 4; kk++) {
            float4 wv = *(const float4*)(sW + (k + kk) * 132 + cg * 4);
            w[kk][0] = wv.x; w[kk][1] = wv.y; w[kk][2] = wv.z; w[kk][3] = wv.w;
        }
#pragma unroll
        for (int r = 0; r < 8; r++) {
            float4 av = *(const float4*)(sA + (rg * 8 + r) * 132 + k);
#pragma unroll
            for (int c = 0; c < 4; c++)
                acc[r][c] += av.x * w[0][c] + av.y * w[1][c]
                           + av.z * w[2][c] + av.w * w[3][c];
        }
    }

    float4 b = make_float4(0.f, 0.f, 0.f, 0.f);
    if (bias) b = *(const float4*)(bias + cg * 4);
#pragma unroll
    for (int r = 0; r < 8; r++) {
        int gr = row0 + rg * 8 + r;
        if (gr >= M) continue;
        float4 o;
        o.x = acc[r][0] + b.x;
        o.y = acc[r][1] + b.y;
        o.z = acc[r][2] + b.z;
        o.w = acc[r][3] + b.w;
        *(float4*)(C + (size_t)gr * 128 + cg * 4) = o;
    }
}

// ---------------- precompute wv = W^T a (4 vectors of 128) -----------------------
__global__ void wvec_k(const float* __restrict__ W1, const float* __restrict__ a1s,
                       const float* __restrict__ a1d,
                       const float* __restrict__ W2, const float* __restrict__ a2s,
                       const float* __restrict__ a2d)
{
    int d = threadIdx.x;
    float s1 = 0.f, s2 = 0.f, s3 = 0.f, s4 = 0.f;
    for (int k = 0; k < 128; k++) {
        float w1 = W1[k * 128 + d], w2 = W2[k * 128 + d];
        s1 += w1 * a1s[k];
        s2 += w1 * a1d[k];
        s3 += w2 * a2s[k];
        s4 += w2 * a2d[k];
    }
    g_wv[d] = s1; g_wv[128 + d] = s2; g_wv[256 + d] = s3; g_wv[384 + d] = s4;
}

// ---------------- per-node attention scores: warp per node ----------------------
__global__ void scores_k(const float* __restrict__ x, int n)
{
    int gw   = (blockIdx.x * blockDim.x + threadIdx.x) >> 5;
    int lane = threadIdx.x & 31;
    if (gw >= n) return;
    float4 xv = *(const float4*)(x + (size_t)gw * 128 + lane * 4);
    float4 w1 = *(const float4*)(g_wv + lane * 4);
    float4 w2 = *(const float4*)(g_wv + 128 + lane * 4);
    float4 w3 = *(const float4*)(g_wv + 256 + lane * 4);
    float4 w4 = *(const float4*)(g_wv + 384 + lane * 4);
    float s1 = xv.x * w1.x + xv.y * w1.y + xv.z * w1.z + xv.w * w1.w;
    float s2 = xv.x * w2.x + xv.y * w2.y + xv.z * w2.z + xv.w * w2.w;
    float s3 = xv.x * w3.x + xv.y * w3.y + xv.z * w3.z + xv.w * w3.w;
    float s4 = xv.x * w4.x + xv.y * w4.y + xv.z * w4.z + xv.w * w4.w;
#pragma unroll
    for (int o = 16; o; o >>= 1) {
        s1 += __shfl_xor_sync(0xFFFFFFFFu, s1, o);
        s2 += __shfl_xor_sync(0xFFFFFFFFu, s2, o);
        s3 += __shfl_xor_sync(0xFFFFFFFFu, s3, o);
        s4 += __shfl_xor_sync(0xFFFFFFFFu, s4, o);
    }
    if (lane == 0) { g_as1[gw] = s1; g_ad1[gw] = s2; g_as2[gw] = s3; g_ad2[gw] = s4; }
}

// ---------------- init: emax = -inf, den = 0 ------------------------------------
__global__ void init_k()
{
    int i = blockIdx.x * blockDim.x + threadIdx.x;
    if (i < NT) { g_emax1[i] = -CUDART_INF_F; g_den1[i] = 0.f; }
    if (i < NS) { g_emax2[i] = -CUDART_INF_F; g_den2[i] = 0.f; }
}

// ---------------- edge helpers ---------------------------------------------------
__device__ __forceinline__ void atomicMaxF(float* addr, float val)
{
    if (val >= 0.f) atomicMax((int*)addr, __float_as_int(val));
    else            atomicMin((unsigned int*)addr, __float_as_uint(val));
}

__device__ __forceinline__ float leaky(float e) { return e > 0.f ? e : 0.2f * e; }

// pass 1: segment max over kept dst        (indices are int32!)
__global__ void edge_max_k(const int* __restrict__ srcA, const int* __restrict__ dstA,
                           int nE, int srcOff, int dstOff,
                           const float* __restrict__ as_, const float* __restrict__ ad_,
                           float* __restrict__ emax, int keepLo, int keepHi)
{
    int i = blockIdx.x * blockDim.x + threadIdx.x;
    if (i >= nE) return;
    int s, d;
    if (srcA) { s = srcA[i] + srcOff; d = dstA[i] + dstOff; }
    else      { s = srcOff + i; d = s; }
    if (d < keepLo || d >= keepHi) return;
    float e = leaky(as_[s] + ad_[d]);
    atomicMaxF(&emax[d - keepLo], e);
}

// pass 2: segment sum of exp(e - max)
__global__ void edge_sum_k(const int* __restrict__ srcA, const int* __restrict__ dstA,
                           int nE, int srcOff, int dstOff,
                           const float* __restrict__ as_, const float* __restrict__ ad_,
                           const float* __restrict__ emax, float* __restrict__ den,
                           int keepLo, int keepHi)
{
    int i = blockIdx.x * blockDim.x + threadIdx.x;
    if (i >= nE) return;
    int s, d;
    if (srcA) { s = srcA[i] + srcOff; d = dstA[i] + dstOff; }
    else      { s = srcOff + i; d = s; }
    if (d < keepLo || d >= keepHi) return;
    int di = d - keepLo;
    float e = leaky(as_[s] + ad_[d]);
    atomicAdd(&den[di], __expf(e - emax[di]));
}

// pass 3: out[dst] += alpha * h[src]  — warp per edge, red.global.add.v4.f32
__global__ void edge_scatter_k(const int* __restrict__ srcA, const int* __restrict__ dstA,
                               int nE, int srcOff, int dstOff,
                               const float* __restrict__ as_, const float* __restrict__ ad_,
                               const float* __restrict__ emax, const float* __restrict__ den,
                               int keepLo, int keepHi,
                               const float* __restrict__ h, float* __restrict__ out)
{
    int gw   = (blockIdx.x * blockDim.x + threadIdx.x) >> 5;
    int lane = threadIdx.x & 31;
    if (gw >= nE) return;
    int s, d;
    if (srcA) { s = srcA[gw] + srcOff; d = dstA[gw] + dstOff; }
    else      { s = srcOff + gw; d = s; }
    if (d < keepLo || d >= keepHi) return;
    int   di    = d - keepLo;
    float e     = leaky(as_[s] + ad_[d]);
    float alpha = __expf(e - emax[di]) / (den[di] + 1e-16f);
    float4 hv = *(const float4*)(h + (size_t)s * 128 + lane * 4);
    float* o  = out + (size_t)di * 128 + lane * 4;
    asm volatile("red.global.add.v4.f32 [%0], {%1,%2,%3,%4};"
                 :: "l"(o), "f"(hv.x * alpha), "f"(hv.y * alpha),
                    "f"(hv.z * alpha), "f"(hv.w * alpha)
                 : "memory");
}

// ---------------- final ReLU over output ----------------------------------------
__global__ void relu_k(float* __restrict__ o, int n4)
{
    int i = blockIdx.x * blockDim.x + threadIdx.x;
    if (i >= n4) return;
    float4 v = ((float4*)o)[i];
    v.x = v.x > 0.f ? v.x : 0.f;
    v.y = v.y > 0.f ? v.y : 0.f;
    v.z = v.z > 0.f ? v.z : 0.f;
    v.w = v.w > 0.f ? v.w : 0.f;
    ((float4*)o)[i] = v;
}

// ---------------- host launch -----------------------------------------------------
extern "C" void kernel_launch(void* const* d_in, const int* in_sizes, int n_in,
                              void* d_out, int out_size)
{
    const int* edge   = (const int*)d_in[0];
    const int* paper  = (const int*)d_in[1];
    const int* author = (const int*)d_in[2];
    const float* x_s = (const float*)d_in[3];
    const float* x_t = (const float*)d_in[4];
    const float* Ws  = (const float*)d_in[5];
    const float* bs  = (const float*)d_in[6];
    const float* Wt  = (const float*)d_in[7];
    const float* bt  = (const float*)d_in[8];
    const float* W1  = (const float*)d_in[9];
    const float* a1s = (const float*)d_in[10];
    const float* a1d = (const float*)d_in[11];
    const float* W2  = (const float*)d_in[12];
    const float* a2s = (const float*)d_in[13];
    const float* a2d = (const float*)d_in[14];

    const int E  = in_sizes[0] / 2;
    const int Ep = in_sizes[1] / 2;
    const int Ea = in_sizes[2] / 2;

    float *px, *ph1, *ph2;
    cudaGetSymbolAddress((void**)&px,  g_x);
    cudaGetSymbolAddress((void**)&ph1, g_h1);
    cudaGetSymbolAddress((void**)&ph2, g_h2);
    float *pas1, *pad1, *pas2, *pad2;
    cudaGetSymbolAddress((void**)&pas1, g_as1);
    cudaGetSymbolAddress((void**)&pad1, g_ad1);
    cudaGetSymbolAddress((void**)&pas2, g_as2);
    cudaGetSymbolAddress((void**)&pad2, g_ad2);
    float *pemax1, *pden1, *pemax2, *pden2;
    cudaGetSymbolAddress((void**)&pemax1, g_emax1);
    cudaGetSymbolAddress((void**)&pden1,  g_den1);
    cudaGetSymbolAddress((void**)&pemax2, g_emax2);
    cudaGetSymbolAddress((void**)&pden2,  g_den2);

    float* out = (float*)d_out;
    float* out_s = out;                     // conv2 result rows [0, NS)
    float* out_t = out + (size_t)NS * DD;   // conv1 result rows [NS, NN)

    const int GEMM_SMEM = (64 * 132 + 128 * 132) * 4;  // 101376 B
    cudaFuncSetAttribute((const void*)gemm_xWt,
                         cudaFuncAttributeMaxDynamicSharedMemorySize, GEMM_SMEM);

    // 0. zero output, init softmax state
    cudaMemsetAsync(d_out, 0, (size_t)out_size * sizeof(float), 0);
    init_k<<<(NT + 255) / 256, 256>>>();

    // 1. input linears: x = [x_s @ Ws^T + bs ; x_t @ Wt^T + bt]
    gemm_xWt<<<(NS + 63) / 64, 256, GEMM_SMEM>>>(x_s, Ws, bs, px, NS);
    gemm_xWt<<<(NT + 63) / 64, 256, GEMM_SMEM>>>(x_t, Wt, bt, px + (size_t)NS * DD, NT);

    // 2. h1 = x @ W1^T, h2 = x @ W2^T
    gemm_xWt<<<(NN + 63) / 64, 256, GEMM_SMEM>>>(px, W1, nullptr, ph1, NN);
    gemm_xWt<<<(NN + 63) / 64, 256, GEMM_SMEM>>>(px, W2, nullptr, ph2, NN);

    // 3. attention scores: a_s = x·(W^T a_src), a_d = x·(W^T a_dst)
    wvec_k<<<1, 128>>>(W1, a1s, a1d, W2, a2s, a2d);
    scores_k<<<(NN * 32 + 255) / 256, 256>>>(px, NN);

    // ----- conv1: edges (edge src->dst+NS), author edges, self-loops; keep dst in [NS, NN)
    // ----- conv2: edges (edge dst+NS -> src), paper edges, self-loops; keep dst in [0, NS)
    const int TB = 256;
    // pass 1: max
    edge_max_k<<<(E  + TB - 1) / TB, TB>>>(edge,      edge + E,   E,  0,  NS, pas1, pad1, pemax1, NS, NN);
    edge_max_k<<<(Ea + TB - 1) / TB, TB>>>(author,    author + Ea, Ea, 0,  0,  pas1, pad1, pemax1, NS, NN);
    edge_max_k<<<(NT + TB - 1) / TB, TB>>>(nullptr,   nullptr,    NT, NS, 0,  pas1, pad1, pemax1, NS, NN);
    edge_max_k<<<(E  + TB - 1) / TB, TB>>>(edge + E,  edge,       E,  NS, 0,  pas2, pad2, pemax2, 0,  NS);
    edge_max_k<<<(Ep + TB - 1) / TB, TB>>>(paper,     paper + Ep, Ep, 0,  0,  pas2, pad2, pemax2, 0,  NS);
    edge_max_k<<<(NS + TB - 1) / TB, TB>>>(nullptr,   nullptr,    NS, 0,  0,  pas2, pad2, pemax2, 0,  NS);
    // pass 2: denom
    edge_sum_k<<<(E  + TB - 1) / TB, TB>>>(edge,      edge + E,   E,  0,  NS, pas1, pad1, pemax1, pden1, NS, NN);
    edge_sum_k<<<(Ea + TB - 1) / TB, TB>>>(author,    author + Ea, Ea, 0,  0,  pas1, pad1, pemax1, pden1, NS, NN);
    edge_sum_k<<<(NT + TB - 1) / TB, TB>>>(nullptr,   nullptr,    NT, NS, 0,  pas1, pad1, pemax1, pden1, NS, NN);
    edge_sum_k<<<(E  + TB - 1) / TB, TB>>>(edge + E,  edge,       E,  NS, 0,  pas2, pad2, pemax2, pden2, 0, NS);
    edge_sum_k<<<(Ep + TB - 1) / TB, TB>>>(paper,     paper + Ep, Ep, 0,  0,  pas2, pad2, pemax2, pden2, 0, NS);
    edge_sum_k<<<(NS + TB - 1) / TB, TB>>>(nullptr,   nullptr,    NS, 0,  0,  pas2, pad2, pemax2, pden2, 0, NS);
    // pass 3: scatter (warp per edge)
    edge_scatter_k<<<(int)(((long long)E  * 32 + TB - 1) / TB), TB>>>(edge,     edge + E,   E,  0,  NS, pas1, pad1, pemax1, pden1, NS, NN, ph1, out_t);
    edge_scatter_k<<<(int)(((long long)Ea * 32 + TB - 1) / TB), TB>>>(author,   author + Ea, Ea, 0,  0,  pas1, pad1, pemax1, pden1, NS, NN, ph1, out_t);
    edge_scatter_k<<<(int)(((long long)NT * 32 + TB - 1) / TB), TB>>>(nullptr,  nullptr,    NT, NS, 0,  pas1, pad1, pemax1, pden1, NS, NN, ph1, out_t);
    edge_scatter_k<<<(int)(((long long)E  * 32 + TB - 1) / TB), TB>>>(edge + E, edge,       E,  NS, 0,  pas2, pad2, pemax2, pden2, 0,  NS, ph2, out_s);
    edge_scatter_k<<<(int)(((long long)Ep * 32 + TB - 1) / TB), TB>>>(paper,    paper + Ep, Ep, 0,  0,  pas2, pad2, pemax2, pden2, 0,  NS, ph2, out_s);
    edge_scatter_k<<<(int)(((long long)NS * 32 + TB - 1) / TB), TB>>>(nullptr,  nullptr,    NS, 0,  0,  pas2, pad2, pemax2, pden2, 0,  NS, ph2, out_s);

    // 4. final ReLU
    relu_k<<<(out_size / 4 + 255) / 256, 256>>>(out, out_size / 4);
}

// round 4
// speedup vs baseline: 1.3062x; 1.3062x over previous
#include <cuda_runtime.h>
#include <cstdint>

#define NS 50000
#define NT 50000
#define NN 100000
#define DD 128

// ---------------- scratch (device globals: no runtime allocation) ----------------
static __device__ float g_x   [NN * DD];
static __device__ float g_agg1[NT * DD];   // conv1: sum_e exp(e) * x[src], dst-NS indexed
static __device__ float g_agg2[NS * DD];   // conv2: sum_e exp(e) * x[src], dst indexed
static __device__ float g_as1[NN], g_ad1[NN], g_as2[NN], g_ad2[NN];
static __device__ float g_den1[NT];
static __device__ float g_den2[NS];
static __device__ float g_wv[4 * DD];

// ---------------- GEMM: C[M,128] = rowscale(A)[M,128] @ W[128,128]^T (+bias, relu)
// BM=64 rows/block, 256 threads, whole K=128 resident in smem.
// If den != nullptr, A row r is scaled by 1/(den[r]+1e-16) on load.
__global__ __launch_bounds__(256, 2)
void gemm_xWt(const float* __restrict__ A, const float* __restrict__ W,
              const float* __restrict__ bias, float* __restrict__ C, int M,
              const float* __restrict__ den, int doRelu)
{
    extern __shared__ float sm[];
    float* sA = sm;              // 64 * 132
    float* sW = sm + 64 * 132;   // 128 * 132, sW[k][j] = W[j][k]
    const int tid  = threadIdx.x;
    const int row0 = blockIdx.x * 64;

    for (int i = tid; i < 4096; i += 256) {
        int j  = i & 127;
        int k4 = (i >> 7) << 2;
        float4 w = *(const float4*)(W + j * 128 + k4);
        sW[(k4 + 0) * 132 + j] = w.x;
        sW[(k4 + 1) * 132 + j] = w.y;
        sW[(k4 + 2) * 132 + j] = w.z;
        sW[(k4 + 3) * 132 + j] = w.w;
    }
    for (int i = tid; i < 64 * 32; i += 256) {
        int r  = i >> 5;
        int k4 = (i & 31) << 2;
        int gr = row0 + r;
        float4 v = make_float4(0.f, 0.f, 0.f, 0.f);
        if (gr < M) {
            v = *(const float4*)(A + (size_t)gr * 128 + k4);
            if (den) {
                float rc = __frcp_rn(den[gr] + 1e-16f);
                v.x *= rc; v.y *= rc; v.z *= rc; v.w *= rc;
            }
        }
        *(float4*)(sA + r * 132 + k4) = v;
    }
    __syncthreads();

    const int rg = tid >> 5;
    const int cg = tid & 31;
    float acc[8][4] = {};

#pragma unroll 4
    for (int k = 0; k < 128; k += 4) {
        float w[4][4];
#pragma unroll
        for (int kk = 0; kk < 4; kk++) {
            float4 wv = *(const float4*)(sW + (k + kk) * 132 + cg * 4);
            w[kk][0] = wv.x; w[kk][1] = wv.y; w[kk][2] = wv.z; w[kk][3] = wv.w;
        }
#pragma unroll
        for (int r = 0; r < 8; r++) {
            float4 av = *(const float4*)(sA + (rg * 8 + r) * 132 + k);
#pragma unroll
            for (int c = 0; c < 4; c++)
                acc[r][c] += av.x * w[0][c] + av.y * w[1][c]
                           + av.z * w[2][c] + av.w * w[3][c];
        }
    }

    float4 b = make_float4(0.f, 0.f, 0.f, 0.f);
    if (bias) b = *(const float4*)(bias + cg * 4);
#pragma unroll
    for (int r = 0; r < 8; r++) {
        int gr = row0 + rg * 8 + r;
        if (gr >= M) continue;
        float4 o;
        o.x = acc[r][0] + b.x;
        o.y = acc[r][1] + b.y;
        o.z = acc[r][2] + b.z;
        o.w = acc[r][3] + b.w;
        if (doRelu) {
            o.x = o.x > 0.f ? o.x : 0.f;
            o.y = o.y > 0.f ? o.y : 0.f;
            o.z = o.z > 0.f ? o.z : 0.f;
            o.w = o.w > 0.f ? o.w : 0.f;
        }
        *(float4*)(C + (size_t)gr * 128 + cg * 4) = o;
    }
}

// ---------------- precompute wv = W^T a (4 vectors of 128) -----------------------
__global__ void wvec_k(const float* __restrict__ W1, const float* __restrict__ a1s,
                       const float* __restrict__ a1d,
                       const float* __restrict__ W2, const float* __restrict__ a2s,
                       const float* __restrict__ a2d)
{
    int d = threadIdx.x;
    float s1 = 0.f, s2 = 0.f, s3 = 0.f, s4 = 0.f;
    for (int k = 0; k < 128; k++) {
        float w1 = W1[k * 128 + d], w2 = W2[k * 128 + d];
        s1 += w1 * a1s[k];
        s2 += w1 * a1d[k];
        s3 += w2 * a2s[k];
        s4 += w2 * a2d[k];
    }
    g_wv[d] = s1; g_wv[128 + d] = s2; g_wv[256 + d] = s3; g_wv[384 + d] = s4;
}

// ---------------- per-node attention scores: warp per node ----------------------
__global__ void scores_k(const float* __restrict__ x, int n)
{
    int gw   = (blockIdx.x * blockDim.x + threadIdx.x) >> 5;
    int lane = threadIdx.x & 31;
    if (gw >= n) return;
    float4 xv = *(const float4*)(x + (size_t)gw * 128 + lane * 4);
    float4 w1 = *(const float4*)(g_wv + lane * 4);
    float4 w2 = *(const float4*)(g_wv + 128 + lane * 4);
    float4 w3 = *(const float4*)(g_wv + 256 + lane * 4);
    float4 w4 = *(const float4*)(g_wv + 384 + lane * 4);
    float s1 = xv.x * w1.x + xv.y * w1.y + xv.z * w1.z + xv.w * w1.w;
    float s2 = xv.x * w2.x + xv.y * w2.y + xv.z * w2.z + xv.w * w2.w;
    float s3 = xv.x * w3.x + xv.y * w3.y + xv.z * w3.z + xv.w * w3.w;
    float s4 = xv.x * w4.x + xv.y * w4.y + xv.z * w4.z + xv.w * w4.w;
#pragma unroll
    for (int o = 16; o; o >>= 1) {
        s1 += __shfl_xor_sync(0xFFFFFFFFu, s1, o);
        s2 += __shfl_xor_sync(0xFFFFFFFFu, s2, o);
        s3 += __shfl_xor_sync(0xFFFFFFFFu, s3, o);
        s4 += __shfl_xor_sync(0xFFFFFFFFu, s4, o);
    }
    if (lane == 0) { g_as1[gw] = s1; g_ad1[gw] = s2; g_as2[gw] = s3; g_ad2[gw] = s4; }
}

__device__ __forceinline__ float leaky(float e) { return e > 0.f ? e : 0.2f * e; }

// ------------- fused edge pass: den[d] += exp(e); agg[d] += exp(e) * x[src] ------
// warp per edge; softmax normalization is deferred to the final GEMM.
__global__ void edge_fused_k(const int* __restrict__ srcA, const int* __restrict__ dstA,
                             int nE, int srcOff, int dstOff,
                             const float* __restrict__ as_, const float* __restrict__ ad_,
                             float* __restrict__ den, int keepLo, int keepHi,
                             const float* __restrict__ x, float* __restrict__ agg)
{
    int gw   = (blockIdx.x * blockDim.x + threadIdx.x) >> 5;
    int lane = threadIdx.x & 31;
    if (gw >= nE) return;
    int s, d;
    if (srcA) { s = srcA[gw] + srcOff; d = dstA[gw] + dstOff; }
    else      { s = srcOff + gw; d = s; }
    if (d < keepLo || d >= keepHi) return;
    int   di = d - keepLo;
    float w  = __expf(leaky(as_[s] + ad_[d]));
    if (lane == 0) atomicAdd(&den[di], w);
    float4 xv = *(const float4*)(x + (size_t)s * 128 + lane * 4);
    float* o  = agg + (size_t)di * 128 + lane * 4;
    asm volatile("red.global.add.v4.f32 [%0], {%1,%2,%3,%4};"
                 :: "l"(o), "f"(xv.x * w), "f"(xv.y * w),
                    "f"(xv.z * w), "f"(xv.w * w)
                 : "memory");
}

// ---------------- host launch -----------------------------------------------------
extern "C" void kernel_launch(void* const* d_in, const int* in_sizes, int n_in,
                              void* d_out, int out_size)
{
    const int* edge   = (const int*)d_in[0];
    const int* paper  = (const int*)d_in[1];
    const int* author = (const int*)d_in[2];
    const float* x_s = (const float*)d_in[3];
    const float* x_t = (const float*)d_in[4];
    const float* Ws  = (const float*)d_in[5];
    const float* bs  = (const float*)d_in[6];
    const float* Wt  = (const float*)d_in[7];
    const float* bt  = (const float*)d_in[8];
    const float* W1  = (const float*)d_in[9];
    const float* a1s = (const float*)d_in[10];
    const float* a1d = (const float*)d_in[11];
    const float* W2  = (const float*)d_in[12];
    const float* a2s = (const float*)d_in[13];
    const float* a2d = (const float*)d_in[14];

    const int E  = in_sizes[0] / 2;
    const int Ep = in_sizes[1] / 2;
    const int Ea = in_sizes[2] / 2;

    float *px, *pagg1, *pagg2;
    cudaGetSymbolAddress((void**)&px,    g_x);
    cudaGetSymbolAddress((void**)&pagg1, g_agg1);
    cudaGetSymbolAddress((void**)&pagg2, g_agg2);
    float *pas1, *pad1, *pas2, *pad2, *pden1, *pden2;
    cudaGetSymbolAddress((void**)&pas1, g_as1);
    cudaGetSymbolAddress((void**)&pad1, g_ad1);
    cudaGetSymbolAddress((void**)&pas2, g_as2);
    cudaGetSymbolAddress((void**)&pad2, g_ad2);
    cudaGetSymbolAddress((void**)&pden1, g_den1);
    cudaGetSymbolAddress((void**)&pden2, g_den2);

    float* out = (float*)d_out;
    float* out_s = out;                     // conv2 result rows [0, NS)
    float* out_t = out + (size_t)NS * DD;   // conv1 result rows [NS, NN)

    const int GEMM_SMEM = (64 * 132 + 128 * 132) * 4;  // 101376 B
    cudaFuncSetAttribute((const void*)gemm_xWt,
                         cudaFuncAttributeMaxDynamicSharedMemorySize, GEMM_SMEM);

    // 0. zero accumulators (out is fully written by the final GEMMs)
    cudaMemsetAsync(pagg1, 0, (size_t)NT * DD * sizeof(float), 0);
    cudaMemsetAsync(pagg2, 0, (size_t)NS * DD * sizeof(float), 0);
    cudaMemsetAsync(pden1, 0, (size_t)NT * sizeof(float), 0);
    cudaMemsetAsync(pden2, 0, (size_t)NS * sizeof(float), 0);

    // 1. input linears: x = [x_s @ Ws^T + bs ; x_t @ Wt^T + bt]
    gemm_xWt<<<(NS + 63) / 64, 256, GEMM_SMEM>>>(x_s, Ws, bs, px, NS, nullptr, 0);
    gemm_xWt<<<(NT + 63) / 64, 256, GEMM_SMEM>>>(x_t, Wt, bt, px + (size_t)NS * DD, NT, nullptr, 0);

    // 2. attention scores: a_s = x·(W^T a_src), a_d = x·(W^T a_dst)
    wvec_k<<<1, 128>>>(W1, a1s, a1d, W2, a2s, a2d);
    scores_k<<<(NN * 32 + 255) / 256, 256>>>(px, NN);

    // 3. fused edge pass (den + unnormalized aggregation of x rows)
    // conv1: edges (src -> dst+NS), author edges, self-loops; keep dst in [NS, NN)
    // conv2: edges (dst+NS -> src), paper edges, self-loops;  keep dst in [0, NS)
    const int TB = 256;
    edge_fused_k<<<(int)(((long long)E  * 32 + TB - 1) / TB), TB>>>(edge,     edge + E,    E,  0,  NS, pas1, pad1, pden1, NS, NN, px, pagg1);
    edge_fused_k<<<(int)(((long long)Ea * 32 + TB - 1) / TB), TB>>>(author,   author + Ea, Ea, 0,  0,  pas1, pad1, pden1, NS, NN, px, pagg1);
    edge_fused_k<<<(int)(((long long)NT * 32 + TB - 1) / TB), TB>>>(nullptr,  nullptr,     NT, NS, 0,  pas1, pad1, pden1, NS, NN, px, pagg1);
    edge_fused_k<<<(int)(((long long)E  * 32 + TB - 1) / TB), TB>>>(edge + E, edge,        E,  NS, 0,  pas2, pad2, pden2, 0,  NS, px, pagg2);
    edge_fused_k<<<(int)(((long long)Ep * 32 + TB - 1) / TB), TB>>>(paper,    paper + Ep,  Ep, 0,  0,  pas2, pad2, pden2, 0,  NS, px, pagg2);
    edge_fused_k<<<(int)(((long long)NS * 32 + TB - 1) / TB), TB>>>(nullptr,  nullptr,     NS, 0,  0,  pas2, pad2, pden2, 0,  NS, px, pagg2);

    // 4. output transforms: out = relu( (agg/den) @ W^T ), normalization fused
    gemm_xWt<<<(NT + 63) / 64, 256, GEMM_SMEM>>>(pagg1, W1, nullptr, out_t, NT, pden1, 1);
    gemm_xWt<<<(NS + 63) / 64, 256, GEMM_SMEM>>>(pagg2, W2, nullptr, out_s, NS, pden2, 1);
}

// round 5
// speedup vs baseline: 1.9326x; 1.4796x over previous
#include <cuda_runtime.h>
#include <cstdint>

#define NS 50000
#define NT 50000
#define NN 100000
#define DD 128
#define CAP 2200000           // max kept edges across both convs (2E+Ea+Ep+NS+NT = 2.1M)
#define NB  ((NN + 255) / 256)

// ---------------- scratch (device globals: no runtime allocation) ----------------
static __device__ float g_x  [NN * DD];
static __device__ float g_agg[NN * DD];   // rows [0,NS): conv2 agg (normalized); [NS,NN): conv1
static __device__ float g_as1[NN], g_ad1[NN], g_as2[NN], g_ad2[NN];
static __device__ float g_wv[4 * DD];
static __device__ int   g_deg[NN];
static __device__ int   g_rowptr[NN];
static __device__ int   g_cur[NN];
static __device__ int   g_part[512];
static __device__ int   g_esrc[CAP];
static __device__ float g_ew  [CAP];

// ---------------- GEMM: C[M,128] = A[M,128] @ W[128,128]^T (+bias, relu) ---------
// BM=64 rows/block, 256 threads, K=128 resident. Optionally fuses the 4 attention
// score dot-products into the epilogue (scores of THIS gemm's output rows).
__global__ __launch_bounds__(256, 2)
void gemm_xWt(const float* __restrict__ A, const float* __restrict__ W,
              const float* __restrict__ bias, float* __restrict__ C, int M,
              int doRelu, int doScores, int scoreOff)
{
    extern __shared__ float sm[];
    float* sA = sm;              // 64 * 132
    float* sW = sm + 64 * 132;   // 128 * 132, sW[k][j] = W[j][k]
    const int tid  = threadIdx.x;
    const int row0 = blockIdx.x * 64;

    for (int i = tid; i < 4096; i += 256) {
        int j  = i & 127;
        int k4 = (i >> 7) << 2;
        float4 w = *(const float4*)(W + j * 128 + k4);
        sW[(k4 + 0) * 132 + j] = w.x;
        sW[(k4 + 1) * 132 + j] = w.y;
        sW[(k4 + 2) * 132 + j] = w.z;
        sW[(k4 + 3) * 132 + j] = w.w;
    }
    for (int i = tid; i < 64 * 32; i += 256) {
        int r  = i >> 5;
        int k4 = (i & 31) << 2;
        int gr = row0 + r;
        float4 v = make_float4(0.f, 0.f, 0.f, 0.f);
        if (gr < M) v = *(const float4*)(A + (size_t)gr * 128 + k4);
        *(float4*)(sA + r * 132 + k4) = v;
    }
    __syncthreads();

    const int rg = tid >> 5;
    const int cg = tid & 31;
    float acc[8][4] = {};

#pragma unroll 4
    for (int k = 0; k < 128; k += 4) {
        float w[4][4];
#pragma unroll
        for (int kk = 0; kk < 4; kk++) {
            float4 wv = *(const float4*)(sW + (k + kk) * 132 + cg * 4);
            w[kk][0] = wv.x; w[kk][1] = wv.y; w[kk][2] = wv.z; w[kk][3] = wv.w;
        }
#pragma unroll
        for (int r = 0; r < 8; r++) {
            float4 av = *(const float4*)(sA + (rg * 8 + r) * 132 + k);
#pragma unroll
            for (int c = 0; c < 4; c++)
                acc[r][c] += av.x * w[0][c] + av.y * w[1][c]
                           + av.z * w[2][c] + av.w * w[3][c];
        }
    }

    float4 b = make_float4(0.f, 0.f, 0.f, 0.f);
    if (bias) b = *(const float4*)(bias + cg * 4);

    float4 v1, v2, v3, v4;
    if (doScores) {
        v1 = *(const float4*)(g_wv + cg * 4);
        v2 = *(const float4*)(g_wv + 128 + cg * 4);
        v3 = *(const float4*)(g_wv + 256 + cg * 4);
        v4 = *(const float4*)(g_wv + 384 + cg * 4);
    }

#pragma unroll
    for (int r = 0; r < 8; r++) {
        int gr = row0 + rg * 8 + r;
        if (gr >= M) continue;
        float4 o;
        o.x = acc[r][0] + b.x;
        o.y = acc[r][1] + b.y;
        o.z = acc[r][2] + b.z;
        o.w = acc[r][3] + b.w;
        if (doScores) {
            float s1 = o.x * v1.x + o.y * v1.y + o.z * v1.z + o.w * v1.w;
            float s2 = o.x * v2.x + o.y * v2.y + o.z * v2.z + o.w * v2.w;
            float s3 = o.x * v3.x + o.y * v3.y + o.z * v3.z + o.w * v3.w;
            float s4 = o.x * v4.x + o.y * v4.y + o.z * v4.z + o.w * v4.w;
#pragma unroll
            for (int of = 16; of; of >>= 1) {
                s1 += __shfl_xor_sync(0xFFFFFFFFu, s1, of);
                s2 += __shfl_xor_sync(0xFFFFFFFFu, s2, of);
                s3 += __shfl_xor_sync(0xFFFFFFFFu, s3, of);
                s4 += __shfl_xor_sync(0xFFFFFFFFu, s4, of);
            }
            if (cg == 0) {
                int n = scoreOff + gr;
                g_as1[n] = s1; g_ad1[n] = s2; g_as2[n] = s3; g_ad2[n] = s4;
            }
        }
        if (doRelu) {
            o.x = o.x > 0.f ? o.x : 0.f;
            o.y = o.y > 0.f ? o.y : 0.f;
            o.z = o.z > 0.f ? o.z : 0.f;
            o.w = o.w > 0.f ? o.w : 0.f;
        }
        *(float4*)(C + (size_t)gr * 128 + cg * 4) = o;
    }
}

// ---------------- precompute wv = W^T a (4 vectors of 128) -----------------------
__global__ void wvec_k(const float* __restrict__ W1, const float* __restrict__ a1s,
                       const float* __restrict__ a1d,
                       const float* __restrict__ W2, const float* __restrict__ a2s,
                       const float* __restrict__ a2d)
{
    int d = threadIdx.x;
    float s1 = 0.f, s2 = 0.f, s3 = 0.f, s4 = 0.f;
    for (int k = 0; k < 128; k++) {
        float w1 = W1[k * 128 + d], w2 = W2[k * 128 + d];
        s1 += w1 * a1s[k];
        s2 += w1 * a1d[k];
        s3 += w2 * a2s[k];
        s4 += w2 * a2d[k];
    }
    g_wv[d] = s1; g_wv[128 + d] = s2; g_wv[256 + d] = s3; g_wv[384 + d] = s4;
}

__device__ __forceinline__ float leaky(float e) { return e > 0.f ? e : 0.2f * e; }

// ---------------- combined edge decomposition ------------------------------------
// segments over one flat index space (kept edges of BOTH convs):
//   [0,E)            conv1 bipartite   s=edge[0][i],      d=edge[1][i]+NS
//   [.., +Ea)        conv1 author      s=author[0][i],    d=author[1][i]   keep d>=NS
//   [.., +NT)        conv1 self-loop   s=d=NS+i
//   [.., +E)         conv2 bipartite   s=edge[1][i]+NS,   d=edge[0][i]
//   [.., +Ep)        conv2 paper       s=paper[0][i],     d=paper[1][i]    keep d<NS
//   [.., +NS)        conv2 self-loop   s=d=i
__device__ __forceinline__ bool decomp_edge(int i, const int* edge, const int* paper,
                                            const int* author, int E, int Ep, int Ea,
                                            int& s, int& d, int& conv1)
{
    if (i < E) { s = edge[i]; d = edge[E + i] + NS; conv1 = 1; return true; }
    i -= E;
    if (i < Ea) { s = author[i]; d = author[Ea + i]; conv1 = 1; return d >= NS; }
    i -= Ea;
    if (i < NT) { s = d = NS + i; conv1 = 1; return true; }
    i -= NT;
    if (i < E) { s = edge[E + i] + NS; d = edge[i]; conv1 = 0; return true; }
    i -= E;
    if (i < Ep) { s = paper[i]; d = paper[Ep + i]; conv1 = 0; return d < NS; }
    i -= Ep;
    if (i < NS) { s = d = i; conv1 = 0; return true; }
    return false;
}

// ---------------- CSR build: histogram ------------------------------------------
__global__ void hist_k(const int* __restrict__ edge, const int* __restrict__ paper,
                       const int* __restrict__ author, int E, int Ep, int Ea, int T)
{
    int i = blockIdx.x * blockDim.x + threadIdx.x;
    if (i >= T) return;
    int s, d, c1;
    if (decomp_edge(i, edge, paper, author, E, Ep, Ea, s, d, c1))
        atomicAdd(&g_deg[d], 1);
}

// ---------------- CSR build: 3-phase exclusive scan over g_deg -------------------
__global__ void scan1_k()
{
    __shared__ int sm[256];
    int t = threadIdx.x;
    int i = blockIdx.x * 256 + t;
    int v = (i < NN) ? g_deg[i] : 0;
    sm[t] = v; __syncthreads();
#pragma unroll
    for (int off = 1; off < 256; off <<= 1) {
        int u = (t >= off) ? sm[t - off] : 0;
        __syncthreads();
        sm[t] += u;
        __syncthreads();
    }
    if (i < NN) g_rowptr[i] = sm[t] - v;         // exclusive within block
    if (t == 255) g_part[blockIdx.x] = sm[255];  // block total
}

__global__ void scan2_k(int nb)
{
    __shared__ int sm[512];
    int t = threadIdx.x;
    int v = (t < nb) ? g_part[t] : 0;
    sm[t] = v; __syncthreads();
#pragma unroll
    for (int off = 1; off < 512; off <<= 1) {
        int u = (t >= off) ? sm[t - off] : 0;
        __syncthreads();
        sm[t] += u;
        __syncthreads();
    }
    if (t < nb) g_part[t] = sm[t] - v;           // exclusive over blocks
}

__global__ void scan3_k()
{
    int i = blockIdx.x * 256 + threadIdx.x;
    if (i >= NN) return;
    int rp = g_rowptr[i] + g_part[blockIdx.x];
    g_rowptr[i] = rp;
    g_cur[i]    = rp;
}

// ---------------- CSR build: fill (src, w) per row -------------------------------
__global__ void fill_k(const int* __restrict__ edge, const int* __restrict__ paper,
                       const int* __restrict__ author, int E, int Ep, int Ea, int T)
{
    int i = blockIdx.x * blockDim.x + threadIdx.x;
    if (i >= T) return;
    int s, d, c1;
    if (!decomp_edge(i, edge, paper, author, E, Ep, Ea, s, d, c1)) return;
    float e = c1 ? (g_as1[s] + g_ad1[d]) : (g_as2[s] + g_ad2[d]);
    float w = __expf(leaky(e));
    int pos = atomicAdd(&g_cur[d], 1);
    if (pos < CAP) { g_esrc[pos] = s; g_ew[pos] = w; }
}

// ---------------- SpMM: warp per dst row; agg[r] = (sum w*x[src]) / (sum w) ------
__global__ __launch_bounds__(256)
void spmm_k(const float* __restrict__ x)
{
    int r    = (blockIdx.x * blockDim.x + threadIdx.x) >> 5;
    int lane = threadIdx.x & 31;
    if (r >= NN) return;
    int start = g_rowptr[r];
    int n     = g_deg[r];
    float4 acc = make_float4(0.f, 0.f, 0.f, 0.f);
    float  den = 0.f;
#pragma unroll 2
    for (int e = 0; e < n; e++) {
        int   src = __ldg(g_esrc + start + e);
        float w   = __ldg(g_ew   + start + e);
        float4 xv = *(const float4*)(x + (size_t)src * 128 + lane * 4);
        acc.x += w * xv.x; acc.y += w * xv.y;
        acc.z += w * xv.z; acc.w += w * xv.w;
        den   += w;
    }
    float rc = __frcp_rn(den + 1e-16f);
    acc.x *= rc; acc.y *= rc; acc.z *= rc; acc.w *= rc;
    *(float4*)(g_agg + (size_t)r * 128 + lane * 4) = acc;
}

// ---------------- host launch -----------------------------------------------------
extern "C" void kernel_launch(void* const* d_in, const int* in_sizes, int n_in,
                              void* d_out, int out_size)
{
    const int* edge   = (const int*)d_in[0];
    const int* paper  = (const int*)d_in[1];
    const int* author = (const int*)d_in[2];
    const float* x_s = (const float*)d_in[3];
    const float* x_t = (const float*)d_in[4];
    const float* Ws  = (const float*)d_in[5];
    const float* bs  = (const float*)d_in[6];
    const float* Wt  = (const float*)d_in[7];
    const float* bt  = (const float*)d_in[8];
    const float* W1  = (const float*)d_in[9];
    const float* a1s = (const float*)d_in[10];
    const float* a1d = (const float*)d_in[11];
    const float* W2  = (const float*)d_in[12];
    const float* a2s = (const float*)d_in[13];
    const float* a2d = (const float*)d_in[14];

    const int E  = in_sizes[0] / 2;
    const int Ep = in_sizes[1] / 2;
    const int Ea = in_sizes[2] / 2;
    const int T  = 2 * E + Ea + Ep + NS + NT;   // combined edge index space

    float *px, *pagg;
    cudaGetSymbolAddress((void**)&px,   g_x);
    cudaGetSymbolAddress((void**)&pagg, g_agg);
    int* pdeg;
    cudaGetSymbolAddress((void**)&pdeg, g_deg);

    float* out = (float*)d_out;
    float* out_s = out;                     // conv2 result rows [0, NS)
    float* out_t = out + (size_t)NS * DD;   // conv1 result rows [NS, NN)

    const int GEMM_SMEM = (64 * 132 + 128 * 132) * 4;  // 101376 B
    cudaFuncSetAttribute((const void*)gemm_xWt,
                         cudaFuncAttributeMaxDynamicSharedMemorySize, GEMM_SMEM);

    // 0. zero degree histogram
    cudaMemsetAsync(pdeg, 0, NN * sizeof(int), 0);

    // 1. score projection vectors, then input linears with fused score epilogue
    wvec_k<<<1, 128>>>(W1, a1s, a1d, W2, a2s, a2d);
    gemm_xWt<<<(NS + 63) / 64, 256, GEMM_SMEM>>>(x_s, Ws, bs, px, NS, 0, 1, 0);
    gemm_xWt<<<(NT + 63) / 64, 256, GEMM_SMEM>>>(x_t, Wt, bt, px + (size_t)NS * DD, NT, 0, 1, NS);

    // 2. CSR build over both convs' kept edges
    const int TB = 256;
    hist_k<<<(T + TB - 1) / TB, TB>>>(edge, paper, author, E, Ep, Ea, T);
    scan1_k<<<NB, 256>>>();
    scan2_k<<<1, 512>>>(NB);
    scan3_k<<<NB, 256>>>();
    fill_k<<<(T + TB - 1) / TB, TB>>>(edge, paper, author, E, Ep, Ea, T);

    // 3. SpMM: normalized aggregation of x rows (no feature atomics)
    spmm_k<<<(NN * 32 + TB - 1) / TB, TB>>>(px);

    // 4. output transforms: out = relu( agg @ W^T )
    gemm_xWt<<<(NT + 63) / 64, 256, GEMM_SMEM>>>(pagg + (size_t)NS * DD, W1, nullptr, out_t, NT, 1, 0, 0);
    gemm_xWt<<<(NS + 63) / 64, 256, GEMM_SMEM>>>(pagg, W2, nullptr, out_s, NS, 1, 0, 0);
}

// round 6
// speedup vs baseline: 1.9328x; 1.0001x over previous
#include <cuda_runtime.h>
#include <cstdint>

#define NS 50000
#define NT 50000
#define NN 100000
#define DD 128
#define CAP 2200000           // max kept edges across both convs (2E+Ea+Ep+NS+NT = 2.1M)
#define NB  ((NN + 255) / 256)

// ---------------- scratch (device globals: no runtime allocation) ----------------
static __device__ float g_x  [NN * DD];
static __device__ float g_agg[NN * DD];   // rows [0,NS): conv2 agg (normalized); [NS,NN): conv1
static __device__ float g_as1[NN], g_ad1[NN], g_as2[NN], g_ad2[NN];
static __device__ float g_wv[4 * DD];
static __device__ int   g_deg[NN];
static __device__ int   g_rowptr[NN];
static __device__ int   g_cur[NN];
static __device__ int   g_part[512];
static __device__ int   g_esrc[CAP];
static __device__ float g_ew  [CAP];

// ---------------- GEMM: C[M,128] = A[M,128] @ W[128,128]^T (+bias, relu) ---------
// BM=64 rows/block, 256 threads, K=128 resident. Optionally fuses the 4 attention
// score dot-products into the epilogue (scores of THIS gemm's output rows).
__global__ __launch_bounds__(256, 2)
void gemm_xWt(const float* __restrict__ A, const float* __restrict__ W,
              const float* __restrict__ bias, float* __restrict__ C, int M,
              int doRelu, int doScores, int scoreOff)
{
    extern __shared__ float sm[];
    float* sA = sm;              // 64 * 132
    float* sW = sm + 64 * 132;   // 128 * 132, sW[k][j] = W[j][k]
    const int tid  = threadIdx.x;
    const int row0 = blockIdx.x * 64;

    for (int i = tid; i < 4096; i += 256) {
        int j  = i & 127;
        int k4 = (i >> 7) << 2;
        float4 w = *(const float4*)(W + j * 128 + k4);
        sW[(k4 + 0) * 132 + j] = w.x;
        sW[(k4 + 1) * 132 + j] = w.y;
        sW[(k4 + 2) * 132 + j] = w.z;
        sW[(k4 + 3) * 132 + j] = w.w;
    }
    for (int i = tid; i < 64 * 32; i += 256) {
        int r  = i >> 5;
        int k4 = (i & 31) << 2;
        int gr = row0 + r;
        float4 v = make_float4(0.f, 0.f, 0.f, 0.f);
        if (gr < M) v = *(const float4*)(A + (size_t)gr * 128 + k4);
        *(float4*)(sA + r * 132 + k4) = v;
    }
    __syncthreads();

    const int rg = tid >> 5;
    const int cg = tid & 31;
    float acc[8][4] = {};

#pragma unroll 4
    for (int k = 0; k < 128; k += 4) {
        float w[4][4];
#pragma unroll
        for (int kk = 0; kk < 4; kk++) {
            float4 wv = *(const float4*)(sW + (k + kk) * 132 + cg * 4);
            w[kk][0] = wv.x; w[kk][1] = wv.y; w[kk][2] = wv.z; w[kk][3] = wv.w;
        }
#pragma unroll
        for (int r = 0; r < 8; r++) {
            float4 av = *(const float4*)(sA + (rg * 8 + r) * 132 + k);
#pragma unroll
            for (int c = 0; c < 4; c++)
                acc[r][c] += av.x * w[0][c] + av.y * w[1][c]
                           + av.z * w[2][c] + av.w * w[3][c];
        }
    }

    float4 b = make_float4(0.f, 0.f, 0.f, 0.f);
    if (bias) b = *(const float4*)(bias + cg * 4);

    float4 v1, v2, v3, v4;
    if (doScores) {
        v1 = *(const float4*)(g_wv + cg * 4);
        v2 = *(const float4*)(g_wv + 128 + cg * 4);
        v3 = *(const float4*)(g_wv + 256 + cg * 4);
        v4 = *(const float4*)(g_wv + 384 + cg * 4);
    }

#pragma unroll
    for (int r = 0; r < 8; r++) {
        int gr = row0 + rg * 8 + r;
        if (gr >= M) continue;
        float4 o;
        o.x = acc[r][0] + b.x;
        o.y = acc[r][1] + b.y;
        o.z = acc[r][2] + b.z;
        o.w = acc[r][3] + b.w;
        if (doScores) {
            float s1 = o.x * v1.x + o.y * v1.y + o.z * v1.z + o.w * v1.w;
            float s2 = o.x * v2.x + o.y * v2.y + o.z * v2.z + o.w * v2.w;
            float s3 = o.x * v3.x + o.y * v3.y + o.z * v3.z + o.w * v3.w;
            float s4 = o.x * v4.x + o.y * v4.y + o.z * v4.z + o.w * v4.w;
#pragma unroll
            for (int of = 16; of; of >>= 1) {
                s1 += __shfl_xor_sync(0xFFFFFFFFu, s1, of);
                s2 += __shfl_xor_sync(0xFFFFFFFFu, s2, of);
                s3 += __shfl_xor_sync(0xFFFFFFFFu, s3, of);
                s4 += __shfl_xor_sync(0xFFFFFFFFu, s4, of);
            }
            if (cg == 0) {
                int n = scoreOff + gr;
                g_as1[n] = s1; g_ad1[n] = s2; g_as2[n] = s3; g_ad2[n] = s4;
            }
        }
        if (doRelu) {
            o.x = o.x > 0.f ? o.x : 0.f;
            o.y = o.y > 0.f ? o.y : 0.f;
            o.z = o.z > 0.f ? o.z : 0.f;
            o.w = o.w > 0.f ? o.w : 0.f;
        }
        *(float4*)(C + (size_t)gr * 128 + cg * 4) = o;
    }
}

// ---------------- precompute wv = W^T a (4 vectors of 128) -----------------------
__global__ void wvec_k(const float* __restrict__ W1, const float* __restrict__ a1s,
                       const float* __restrict__ a1d,
                       const float* __restrict__ W2, const float* __restrict__ a2s,
                       const float* __restrict__ a2d)
{
    int d = threadIdx.x;
    float s1 = 0.f, s2 = 0.f, s3 = 0.f, s4 = 0.f;
    for (int k = 0; k < 128; k++) {
        float w1 = W1[k * 128 + d], w2 = W2[k * 128 + d];
        s1 += w1 * a1s[k];
        s2 += w1 * a1d[k];
        s3 += w2 * a2s[k];
        s4 += w2 * a2d[k];
    }
    g_wv[d] = s1; g_wv[128 + d] = s2; g_wv[256 + d] = s3; g_wv[384 + d] = s4;
}

__device__ __forceinline__ float leaky(float e) { return e > 0.f ? e : 0.2f * e; }

// ---------------- combined edge decomposition ------------------------------------
// segments over one flat index space (kept edges of BOTH convs):
//   [0,E)            conv1 bipartite   s=edge[0][i],      d=edge[1][i]+NS
//   [.., +Ea)        conv1 author      s=author[0][i],    d=author[1][i]   keep d>=NS
//   [.., +NT)        conv1 self-loop   s=d=NS+i
//   [.., +E)         conv2 bipartite   s=edge[1][i]+NS,   d=edge[0][i]
//   [.., +Ep)        conv2 paper       s=paper[0][i],     d=paper[1][i]    keep d<NS
//   [.., +NS)        conv2 self-loop   s=d=i
__device__ __forceinline__ bool decomp_edge(int i, const int* edge, const int* paper,
                                            const int* author, int E, int Ep, int Ea,
                                            int& s, int& d, int& conv1)
{
    if (i < E) { s = edge[i]; d = edge[E + i] + NS; conv1 = 1; return true; }
    i -= E;
    if (i < Ea) { s = author[i]; d = author[Ea + i]; conv1 = 1; return d >= NS; }
    i -= Ea;
    if (i < NT) { s = d = NS + i; conv1 = 1; return true; }
    i -= NT;
    if (i < E) { s = edge[E + i] + NS; d = edge[i]; conv1 = 0; return true; }
    i -= E;
    if (i < Ep) { s = paper[i]; d = paper[Ep + i]; conv1 = 0; return d < NS; }
    i -= Ep;
    if (i < NS) { s = d = i; conv1 = 0; return true; }
    return false;
}

// ---------------- CSR build: histogram ------------------------------------------
__global__ void hist_k(const int* __restrict__ edge, const int* __restrict__ paper,
                       const int* __restrict__ author, int E, int Ep, int Ea, int T)
{
    int i = blockIdx.x * blockDim.x + threadIdx.x;
    if (i >= T) return;
    int s, d, c1;
    if (decomp_edge(i, edge, paper, author, E, Ep, Ea, s, d, c1))
        atomicAdd(&g_deg[d], 1);
}

// ---------------- CSR build: 3-phase exclusive scan over g_deg -------------------
__global__ void scan1_k()
{
    __shared__ int sm[256];
    int t = threadIdx.x;
    int i = blockIdx.x * 256 + t;
    int v = (i < NN) ? g_deg[i] : 0;
    sm[t] = v; __syncthreads();
#pragma unroll
    for (int off = 1; off < 256; off <<= 1) {
        int u = (t >= off) ? sm[t - off] : 0;
        __syncthreads();
        sm[t] += u;
        __syncthreads();
    }
    if (i < NN) g_rowptr[i] = sm[t] - v;         // exclusive within block
    if (t == 255) g_part[blockIdx.x] = sm[255];  // block total
}

__global__ void scan2_k(int nb)
{
    __shared__ int sm[512];
    int t = threadIdx.x;
    int v = (t < nb) ? g_part[t] : 0;
    sm[t] = v; __syncthreads();
#pragma unroll
    for (int off = 1; off < 512; off <<= 1) {
        int u = (t >= off) ? sm[t - off] : 0;
        __syncthreads();
        sm[t] += u;
        __syncthreads();
    }
    if (t < nb) g_part[t] = sm[t] - v;           // exclusive over blocks
}

__global__ void scan3_k()
{
    int i = blockIdx.x * 256 + threadIdx.x;
    if (i >= NN) return;
    int rp = g_rowptr[i] + g_part[blockIdx.x];
    g_rowptr[i] = rp;
    g_cur[i]    = rp;
}

// ---------------- CSR build: fill (src, w) per row -------------------------------
__global__ void fill_k(const int* __restrict__ edge, const int* __restrict__ paper,
                       const int* __restrict__ author, int E, int Ep, int Ea, int T)
{
    int i = blockIdx.x * blockDim.x + threadIdx.x;
    if (i >= T) return;
    int s, d, c1;
    if (!decomp_edge(i, edge, paper, author, E, Ep, Ea, s, d, c1)) return;
    float e = c1 ? (g_as1[s] + g_ad1[d]) : (g_as2[s] + g_ad2[d]);
    float w = __expf(leaky(e));
    int pos = atomicAdd(&g_cur[d], 1);
    if (pos < CAP) { g_esrc[pos] = s; g_ew[pos] = w; }
}

// ---------------- SpMM: warp per dst row; agg[r] = (sum w*x[src]) / (sum w) ------
__global__ __launch_bounds__(256)
void spmm_k(const float* __restrict__ x)
{
    int r    = (blockIdx.x * blockDim.x + threadIdx.x) >> 5;
    int lane = threadIdx.x & 31;
    if (r >= NN) return;
    int start = g_rowptr[r];
    int n     = g_deg[r];
    float4 acc = make_float4(0.f, 0.f, 0.f, 0.f);
    float  den = 0.f;
#pragma unroll 2
    for (int e = 0; e < n; e++) {
        int   src = __ldg(g_esrc + start + e);
        float w   = __ldg(g_ew   + start + e);
        float4 xv = *(const float4*)(x + (size_t)src * 128 + lane * 4);
        acc.x += w * xv.x; acc.y += w * xv.y;
        acc.z += w * xv.z; acc.w += w * xv.w;
        den   += w;
    }
    float rc = __frcp_rn(den + 1e-16f);
    acc.x *= rc; acc.y *= rc; acc.z *= rc; acc.w *= rc;
    *(float4*)(g_agg + (size_t)r * 128 + lane * 4) = acc;
}

// ---------------- host launch -----------------------------------------------------
extern "C" void kernel_launch(void* const* d_in, const int* in_sizes, int n_in,
                              void* d_out, int out_size)
{
    const int* edge   = (const int*)d_in[0];
    const int* paper  = (const int*)d_in[1];
    const int* author = (const int*)d_in[2];
    const float* x_s = (const float*)d_in[3];
    const float* x_t = (const float*)d_in[4];
    const float* Ws  = (const float*)d_in[5];
    const float* bs  = (const float*)d_in[6];
    const float* Wt  = (const float*)d_in[7];
    const float* bt  = (const float*)d_in[8];
    const float* W1  = (const float*)d_in[9];
    const float* a1s = (const float*)d_in[10];
    const float* a1d = (const float*)d_in[11];
    const float* W2  = (const float*)d_in[12];
    const float* a2s = (const float*)d_in[13];
    const float* a2d = (const float*)d_in[14];

    const int E  = in_sizes[0] / 2;
    const int Ep = in_sizes[1] / 2;
    const int Ea = in_sizes[2] / 2;
    const int T  = 2 * E + Ea + Ep + NS + NT;   // combined edge index space

    float *px, *pagg;
    cudaGetSymbolAddress((void**)&px,   g_x);
    cudaGetSymbolAddress((void**)&pagg, g_agg);
    int* pdeg;
    cudaGetSymbolAddress((void**)&pdeg, g_deg);

    float* out = (float*)d_out;
    float* out_s = out;                     // conv2 result rows [0, NS)
    float* out_t = out + (size_t)NS * DD;   // conv1 result rows [NS, NN)

    const int GEMM_SMEM = (64 * 132 + 128 * 132) * 4;  // 101376 B
    cudaFuncSetAttribute((const void*)gemm_xWt,
                         cudaFuncAttributeMaxDynamicSharedMemorySize, GEMM_SMEM);

    // 0. zero degree histogram
    cudaMemsetAsync(pdeg, 0, NN * sizeof(int), 0);

    // 1. score projection vectors, then input linears with fused score epilogue
    wvec_k<<<1, 128>>>(W1, a1s, a1d, W2, a2s, a2d);
    gemm_xWt<<<(NS + 63) / 64, 256, GEMM_SMEM>>>(x_s, Ws, bs, px, NS, 0, 1, 0);
    gemm_xWt<<<(NT + 63) / 64, 256, GEMM_SMEM>>>(x_t, Wt, bt, px + (size_t)NS * DD, NT, 0, 1, NS);

    // 2. CSR build over both convs' kept edges
    const int TB = 256;
    hist_k<<<(T + TB - 1) / TB, TB>>>(edge, paper, author, E, Ep, Ea, T);
    scan1_k<<<NB, 256>>>();
    scan2_k<<<1, 512>>>(NB);
    scan3_k<<<NB, 256>>>();
    fill_k<<<(T + TB - 1) / TB, TB>>>(edge, paper, author, E, Ep, Ea, T);

    // 3. SpMM: normalized aggregation of x rows (no feature atomics)
    spmm_k<<<(NN * 32 + TB - 1) / TB, TB>>>(px);

    // 4. output transforms: out = relu( agg @ W^T )
    gemm_xWt<<<(NT + 63) / 64, 256, GEMM_SMEM>>>(pagg + (size_t)NS * DD, W1, nullptr, out_t, NT, 1, 0, 0);
    gemm_xWt<<<(NS + 63) / 64, 256, GEMM_SMEM>>>(pagg, W2, nullptr, out_s, NS, 1, 0, 0);
}

// round 7
// speedup vs baseline: 2.3821x; 1.2325x over previous
#include <cuda_runtime.h>
#include <cstdint>

#define NS 50000
#define NT 50000
#define NN 100000
#define DD 128
#define CAP 2200000
#define NB  ((NN + 255) / 256)

// ---------------- scratch (device globals: no runtime allocation) ----------------
static __device__ float g_x  [NN * DD];
static __device__ float g_agg[NN * DD];   // rows [0,NS): conv2 agg; [NS,NN): conv1
static __device__ float g_sc [4 * NN];    // as1 | ad1 | as2 | ad2
static __device__ float g_wv [4 * DD];
static __device__ int   g_deg[NN];
static __device__ int   g_rowptr[NN];
static __device__ int   g_cur[NN];
static __device__ int   g_part[512];
static __device__ int   g_esrc[CAP];
static __device__ float g_ew  [CAP];

// ---------------- 3xTF32 helpers --------------------------------------------------
__device__ __forceinline__ void split3(float v, uint32_t& hi, uint32_t& lo)
{
    uint32_t h = __float_as_uint(v) & 0xFFFFE000u;
    hi = h;
    lo = __float_as_uint(v - __uint_as_float(h)) & 0xFFFFE000u;
}

#define MMA_TF32(d, a0, a1, a2, a3, b0, b1)                                      \
    asm volatile("mma.sync.aligned.m16n8k8.row.col.f32.tf32.tf32.f32 "           \
        "{%0,%1,%2,%3}, {%4,%5,%6,%7}, {%8,%9}, {%0,%1,%2,%3};"                  \
        : "+f"((d)[0]), "+f"((d)[1]), "+f"((d)[2]), "+f"((d)[3])                 \
        : "r"(a0), "r"(a1), "r"(a2), "r"(a3), "r"(b0), "r"(b1))

// =============== GEMM: C[M,128] = A[M,128] @ W[128,128]^T (+bias,relu,scores) ====
// 64-row tile / 256 threads / 8 warps (4 m-tiles x 2 n-halves). 3xTF32 mma.sync.
// Fragment layout m16n8k8 tf32 (g=lane>>2, tq=lane&3):
//   A: a0=(g,tq) a1=(g+8,tq) a2=(g,tq+4) a3=(g+8,tq+4)     [row-major 16x8]
//   B: b0=(k=tq,n=g) b1=(k=tq+4,n=g)                        [col-major 8x8]
//   C: c0=(g,2tq) c1=(g,2tq+1) c2=(g+8,2tq) c3=(g+8,2tq+1)
__global__ __launch_bounds__(256)
void mma_gemm(const float* __restrict__ A, const float* __restrict__ W,
              const float* __restrict__ bias, float* __restrict__ C, int M,
              int doRelu, int doScores, int scoreOff)
{
    extern __shared__ float sm[];
    float* sA = sm;              // 64 x 132
    float* sW = sm + 64 * 132;   // 128 x 132 (W as-is: [n][k])
    const int tid  = threadIdx.x;
    const int row0 = blockIdx.x * 64;

    for (int i = tid; i < 4096; i += 256) {
        int n  = i >> 5;
        int k4 = (i & 31) << 2;
        *(float4*)(sW + n * 132 + k4) = *(const float4*)(W + n * 128 + k4);
    }
    for (int i = tid; i < 2048; i += 256) {
        int r  = i >> 5;
        int k4 = (i & 31) << 2;
        int gr = row0 + r;
        float4 v = make_float4(0.f, 0.f, 0.f, 0.f);
        if (gr < M) v = *(const float4*)(A + (size_t)gr * 128 + k4);
        *(float4*)(sA + r * 132 + k4) = v;
    }
    __syncthreads();

    const int wid  = tid >> 5;
    const int lane = tid & 31;
    const int mw   = wid & 3;          // m-tile (16 rows)
    const int nb   = (wid >> 2) * 64;  // n-half base
    const int g    = lane >> 2;
    const int tq   = lane & 3;

    float acc[8][4] = {};

#pragma unroll
    for (int k0 = 0; k0 < 128; k0 += 8) {
        const int ra = (mw * 16 + g) * 132 + k0 + tq;
        float a0 = sA[ra], a1 = sA[ra + 8 * 132], a2 = sA[ra + 4], a3 = sA[ra + 8 * 132 + 4];
        uint32_t ah0, al0, ah1, al1, ah2, al2, ah3, al3;
        split3(a0, ah0, al0); split3(a1, ah1, al1);
        split3(a2, ah2, al2); split3(a3, ah3, al3);
#pragma unroll
        for (int nt = 0; nt < 8; nt++) {
            const int rb = (nb + nt * 8 + g) * 132 + k0 + tq;
            float b0 = sW[rb], b1 = sW[rb + 4];
            uint32_t bh0, bl0, bh1, bl1;
            split3(b0, bh0, bl0); split3(b1, bh1, bl1);
            MMA_TF32(acc[nt], ah0, ah1, ah2, ah3, bh0, bh1);
            MMA_TF32(acc[nt], al0, al1, al2, al3, bh0, bh1);
            MMA_TF32(acc[nt], ah0, ah1, ah2, ah3, bl0, bl1);
        }
    }

    // epilogue
    const int r0 = row0 + mw * 16 + g;
    const int r1 = r0 + 8;
    float s0[4] = {}, s1[4] = {};

#pragma unroll
    for (int nt = 0; nt < 8; nt++) {
        int c = nb + nt * 8 + tq * 2;
        float bx = 0.f, by = 0.f;
        if (bias) { float2 b = *(const float2*)(bias + c); bx = b.x; by = b.y; }
        float o00 = acc[nt][0] + bx, o01 = acc[nt][1] + by;
        float o10 = acc[nt][2] + bx, o11 = acc[nt][3] + by;
        if (doScores) {
#pragma unroll
            for (int t = 0; t < 4; t++) {
                float2 w = *(const float2*)(g_wv + t * 128 + c);
                if (r0 < M) s0[t] += o00 * w.x + o01 * w.y;
                if (r1 < M) s1[t] += o10 * w.x + o11 * w.y;
            }
        }
        if (doRelu) {
            o00 = o00 > 0.f ? o00 : 0.f; o01 = o01 > 0.f ? o01 : 0.f;
            o10 = o10 > 0.f ? o10 : 0.f; o11 = o11 > 0.f ? o11 : 0.f;
        }
        if (r0 < M) *(float2*)(C + (size_t)r0 * 128 + c) = make_float2(o00, o01);
        if (r1 < M) *(float2*)(C + (size_t)r1 * 128 + c) = make_float2(o10, o11);
    }

    if (doScores) {
#pragma unroll
        for (int t = 0; t < 4; t++) {
            s0[t] += __shfl_xor_sync(0xFFFFFFFFu, s0[t], 1);
            s0[t] += __shfl_xor_sync(0xFFFFFFFFu, s0[t], 2);
            s1[t] += __shfl_xor_sync(0xFFFFFFFFu, s1[t], 1);
            s1[t] += __shfl_xor_sync(0xFFFFFFFFu, s1[t], 2);
        }
        if (tq == 0) {
#pragma unroll
            for (int t = 0; t < 4; t++) {
                if (r0 < M) atomicAdd(&g_sc[t * NN + scoreOff + r0], s0[t]);
                if (r1 < M) atomicAdd(&g_sc[t * NN + scoreOff + r1], s1[t]);
            }
        }
    }
}

// ---------------- precompute wv = W^T a (4 vectors of 128) -----------------------
__global__ void wvec_k(const float* __restrict__ W1, const float* __restrict__ a1s,
                       const float* __restrict__ a1d,
                       const float* __restrict__ W2, const float* __restrict__ a2s,
                       const float* __restrict__ a2d)
{
    int d = threadIdx.x;
    float s1 = 0.f, s2 = 0.f, s3 = 0.f, s4 = 0.f;
    for (int k = 0; k < 128; k++) {
        float w1 = W1[k * 128 + d], w2 = W2[k * 128 + d];
        s1 += w1 * a1s[k];
        s2 += w1 * a1d[k];
        s3 += w2 * a2s[k];
        s4 += w2 * a2d[k];
    }
    g_wv[d] = s1; g_wv[128 + d] = s2; g_wv[256 + d] = s3; g_wv[384 + d] = s4;
}

__device__ __forceinline__ float leaky(float e) { return e > 0.f ? e : 0.2f * e; }

// ---------------- combined edge decomposition (see R6) ---------------------------
__device__ __forceinline__ bool decomp_edge(int i, const int* edge, const int* paper,
                                            const int* author, int E, int Ep, int Ea,
                                            int& s, int& d, int& conv1)
{
    if (i < E) { s = edge[i]; d = edge[E + i] + NS; conv1 = 1; return true; }
    i -= E;
    if (i < Ea) { s = author[i]; d = author[Ea + i]; conv1 = 1; return d >= NS; }
    i -= Ea;
    if (i < NT) { s = d = NS + i; conv1 = 1; return true; }
    i -= NT;
    if (i < E) { s = edge[E + i] + NS; d = edge[i]; conv1 = 0; return true; }
    i -= E;
    if (i < Ep) { s = paper[i]; d = paper[Ep + i]; conv1 = 0; return d < NS; }
    i -= Ep;
    if (i < NS) { s = d = i; conv1 = 0; return true; }
    return false;
}

__global__ void hist_k(const int* __restrict__ edge, const int* __restrict__ paper,
                       const int* __restrict__ author, int E, int Ep, int Ea, int T)
{
    int i = blockIdx.x * blockDim.x + threadIdx.x;
    if (i >= T) return;
    int s, d, c1;
    if (decomp_edge(i, edge, paper, author, E, Ep, Ea, s, d, c1))
        atomicAdd(&g_deg[d], 1);
}

__global__ void scan1_k()
{
    __shared__ int sm[256];
    int t = threadIdx.x;
    int i = blockIdx.x * 256 + t;
    int v = (i < NN) ? g_deg[i] : 0;
    sm[t] = v; __syncthreads();
#pragma unroll
    for (int off = 1; off < 256; off <<= 1) {
        int u = (t >= off) ? sm[t - off] : 0;
        __syncthreads();
        sm[t] += u;
        __syncthreads();
    }
    if (i < NN) g_rowptr[i] = sm[t] - v;
    if (t == 255) g_part[blockIdx.x] = sm[255];
}

__global__ void scan2_k(int nb)
{
    __shared__ int sm[512];
    int t = threadIdx.x;
    int v = (t < nb) ? g_part[t] : 0;
    sm[t] = v; __syncthreads();
#pragma unroll
    for (int off = 1; off < 512; off <<= 1) {
        int u = (t >= off) ? sm[t - off] : 0;
        __syncthreads();
        sm[t] += u;
        __syncthreads();
    }
    if (t < nb) g_part[t] = sm[t] - v;
}

__global__ void scan3_k()
{
    int i = blockIdx.x * 256 + threadIdx.x;
    if (i >= NN) return;
    int rp = g_rowptr[i] + g_part[blockIdx.x];
    g_rowptr[i] = rp;
    g_cur[i]    = rp;
}

__global__ void fill_k(const int* __restrict__ edge, const int* __restrict__ paper,
                       const int* __restrict__ author, int E, int Ep, int Ea, int T)
{
    int i = blockIdx.x * blockDim.x + threadIdx.x;
    if (i >= T) return;
    int s, d, c1;
    if (!decomp_edge(i, edge, paper, author, E, Ep, Ea, s, d, c1)) return;
    float e = c1 ? (g_sc[s] + g_sc[NN + d]) : (g_sc[2 * NN + s] + g_sc[3 * NN + d]);
    float w = __expf(leaky(e));
    int pos = atomicAdd(&g_cur[d], 1);
    if (pos < CAP) { g_esrc[pos] = s; g_ew[pos] = w; }
}

// ---------------- SpMM: warp per dst row; agg[r] = (sum w*x[src]) / (sum w) ------
__global__ __launch_bounds__(256)
void spmm_k(const float* __restrict__ x)
{
    int r    = (blockIdx.x * blockDim.x + threadIdx.x) >> 5;
    int lane = threadIdx.x & 31;
    if (r >= NN) return;
    int start = g_rowptr[r];
    int n     = g_deg[r];
    float4 acc = make_float4(0.f, 0.f, 0.f, 0.f);
    float  den = 0.f;
#pragma unroll 2
    for (int e = 0; e < n; e++) {
        int   src = __ldg(g_esrc + start + e);
        float w   = __ldg(g_ew   + start + e);
        float4 xv = *(const float4*)(x + (size_t)src * 128 + lane * 4);
        acc.x += w * xv.x; acc.y += w * xv.y;
        acc.z += w * xv.z; acc.w += w * xv.w;
        den   += w;
    }
    float rc = __frcp_rn(den + 1e-16f);
    acc.x *= rc; acc.y *= rc; acc.z *= rc; acc.w *= rc;
    *(float4*)(g_agg + (size_t)r * 128 + lane * 4) = acc;
}

// ---------------- host launch -----------------------------------------------------
extern "C" void kernel_launch(void* const* d_in, const int* in_sizes, int n_in,
                              void* d_out, int out_size)
{
    const int* edge   = (const int*)d_in[0];
    const int* paper  = (const int*)d_in[1];
    const int* author = (const int*)d_in[2];
    const float* x_s = (const float*)d_in[3];
    const float* x_t = (const float*)d_in[4];
    const float* Ws  = (const float*)d_in[5];
    const float* bs  = (const float*)d_in[6];
    const float* Wt  = (const float*)d_in[7];
    const float* bt  = (const float*)d_in[8];
    const float* W1  = (const float*)d_in[9];
    const float* a1s = (const float*)d_in[10];
    const float* a1d = (const float*)d_in[11];
    const float* W2  = (const float*)d_in[12];
    const float* a2s = (const float*)d_in[13];
    const float* a2d = (const float*)d_in[14];

    const int E  = in_sizes[0] / 2;
    const int Ep = in_sizes[1] / 2;
    const int Ea = in_sizes[2] / 2;
    const int T  = 2 * E + Ea + Ep + NS + NT;

    float *px, *pagg, *psc;
    cudaGetSymbolAddress((void**)&px,   g_x);
    cudaGetSymbolAddress((void**)&pagg, g_agg);
    cudaGetSymbolAddress((void**)&psc,  g_sc);
    int* pdeg;
    cudaGetSymbolAddress((void**)&pdeg, g_deg);

    float* out = (float*)d_out;
    float* out_s = out;                     // conv2 result rows [0, NS)
    float* out_t = out + (size_t)NS * DD;   // conv1 result rows [NS, NN)

    const int GEMM_SMEM = (64 * 132 + 128 * 132) * 4;  // 101376 B
    cudaFuncSetAttribute((const void*)mma_gemm,
                         cudaFuncAttributeMaxDynamicSharedMemorySize, GEMM_SMEM);

    // 0. zero degree histogram + score accumulators
    cudaMemsetAsync(pdeg, 0, NN * sizeof(int), 0);
    cudaMemsetAsync(psc,  0, 4 * NN * sizeof(float), 0);

    // 1. score projection vectors, then input linears with fused score epilogue
    wvec_k<<<1, 128>>>(W1, a1s, a1d, W2, a2s, a2d);
    mma_gemm<<<(NS + 63) / 64, 256, GEMM_SMEM>>>(x_s, Ws, bs, px, NS, 0, 1, 0);
    mma_gemm<<<(NT + 63) / 64, 256, GEMM_SMEM>>>(x_t, Wt, bt, px + (size_t)NS * DD, NT, 0, 1, NS);

    // 2. CSR build over both convs' kept edges
    const int TB = 256;
    hist_k<<<(T + TB - 1) / TB, TB>>>(edge, paper, author, E, Ep, Ea, T);
    scan1_k<<<NB, 256>>>();
    scan2_k<<<1, 512>>>(NB);
    scan3_k<<<NB, 256>>>();
    fill_k<<<(T + TB - 1) / TB, TB>>>(edge, paper, author, E, Ep, Ea, T);

    // 3. SpMM: normalized aggregation of x rows
    spmm_k<<<(NN * 32 + TB - 1) / TB, TB>>>(px);

    // 4. output transforms: out = relu( agg @ W^T )
    mma_gemm<<<(NT + 63) / 64, 256, GEMM_SMEM>>>(pagg + (size_t)NS * DD, W1, nullptr, out_t, NT, 1, 0, 0);
    mma_gemm<<<(NS + 63) / 64, 256, GEMM_SMEM>>>(pagg, W2, nullptr, out_s, NS, 1, 0, 0);
}